// round 7
// baseline (speedup 1.0000x reference)
#include <cuda_runtime.h>
#include <cstdint>

#define DT 0.01f

// ---------------- scratch (device globals; no allocations allowed) ----------------
__device__ __align__(16) float g_Pp[128][16][16];   // P_p[t]
__device__ __align__(16) float g_Pf[128][16][16];   // P_f[t]
__device__ __align__(16) float g_K [128][16][8];    // Kalman gain
__device__ __align__(16) float g_G [128][16][16];   // smoother gain (t=0..126)
// per-batch state history [t][b][i]
__device__ float g_sf[128][2048][16];
__device__ float g_sp[128][2048][16];
// producer/consumer sync
__device__ int g_progress;
__device__ int g_done;

// ---------------- cp.async helpers ----------------
__device__ __forceinline__ void cp16(void* dst, const void* src) {
    unsigned d = (unsigned)__cvta_generic_to_shared(dst);
    asm volatile("cp.async.cg.shared.global [%0], [%1], 16;" :: "r"(d), "l"(src));
}
__device__ __forceinline__ void cp_commit() {
    asm volatile("cp.async.commit_group;");
}
template<int N> __device__ __forceinline__ void cp_wait() {
    asm volatile("cp.async.wait_group %0;" :: "n"(N));
}

__global__ void init_sync() { g_progress = 0; g_done = 0; }

#define ST 8   // cp.async ring depth

// =====================================================================
// Fused persistent kernel, grid = 129 CTAs x 256 threads.
//   CTA 0      : serial covariance recursion (proven R2/R4 code) + publish
//   CTA 1..128 : worker w = bid-1, batches [16w, 16w+16):
//                forward filter (consumes K_t as produced, W/V inline),
//                then G_w tile, grid sync, backward smoother.
// =====================================================================
__global__ __launch_bounds__(256)
void fused_kernel(const float* __restrict__ state0,
                  const float* __restrict__ controls,
                  const float* __restrict__ obs,
                  const float* __restrict__ A,
                  const float* __restrict__ Bc,
                  const float* __restrict__ H,
                  const float* __restrict__ Q,
                  const float* __restrict__ R,
                  const float* __restrict__ P0,
                  float* __restrict__ out)
{
    const int tid = threadIdx.x;

    if (blockIdx.x == 0) {
        // ============== producer: covariance / gain recursion ==============
        __shared__ float Psh[16][17];
        __shared__ __align__(16) float tmp[16][20];
        __shared__ __align__(16) float Pp [16][20];
        __shared__ __align__(16) float PHt [16][8];
        __shared__ __align__(16) float PHtT[8][16];
        __shared__ __align__(16) float Ks  [16][8];
        __shared__ __align__(16) float Sinv[8][8];

        const int i = tid >> 4, j = tid & 15;

        float Fi[16], Fj[16];
        #pragma unroll
        for (int k = 0; k < 16; ++k) {
            Fi[k] = ((i == k) ? 1.0f : 0.0f) + DT * A[i * 16 + k];
            Fj[k] = ((j == k) ? 1.0f : 0.0f) + DT * A[j * 16 + k];
        }
        const float Qij = Q[i * 16 + j];
        Psh[i][j] = P0[i * 16 + j];

        const int r3 = tid >> 3, c3 = tid & 7;
        float Hc[16];
        if (tid < 128) {
            #pragma unroll
            for (int q = 0; q < 16; ++q) Hc[q] = H[c3 * 16 + q];
        }

        const int lr = tid >> 2, lc0 = tid & 3, lc1 = lc0 + 4;
        float Hr[16], Rr0 = 0.f, Rr1 = 0.f;
        if (tid < 32) {
            #pragma unroll
            for (int q = 0; q < 16; ++q) Hr[q] = H[lr * 16 + q];
            Rr0 = R[lr * 8 + lc0];
            Rr1 = R[lr * 8 + lc1];
        }
        __syncthreads();

        for (int t = 0; t < 128; ++t) {
            // P1: tmp = F * P
            {
                float a0 = 0.f, a1 = 0.f, a2 = 0.f, a3 = 0.f;
                #pragma unroll
                for (int k = 0; k < 16; k += 4) {
                    a0 += Fi[k + 0] * Psh[k + 0][j];
                    a1 += Fi[k + 1] * Psh[k + 1][j];
                    a2 += Fi[k + 2] * Psh[k + 2][j];
                    a3 += Fi[k + 3] * Psh[k + 3][j];
                }
                tmp[i][j] = (a0 + a1) + (a2 + a3);
            }
            __syncthreads();

            // P2: Pp = tmp * F^T + Q
            {
                const float4* tr = reinterpret_cast<const float4*>(&tmp[i][0]);
                float4 t0 = tr[0], t1 = tr[1], t2 = tr[2], t3 = tr[3];
                float a0 = Qij, a1 = 0.f, a2 = 0.f, a3 = 0.f;
                a0 += t0.x * Fj[0];  a1 += t0.y * Fj[1];  a2 += t0.z * Fj[2];  a3 += t0.w * Fj[3];
                a0 += t1.x * Fj[4];  a1 += t1.y * Fj[5];  a2 += t1.z * Fj[6];  a3 += t1.w * Fj[7];
                a0 += t2.x * Fj[8];  a1 += t2.y * Fj[9];  a2 += t2.z * Fj[10]; a3 += t2.w * Fj[11];
                a0 += t3.x * Fj[12]; a1 += t3.y * Fj[13]; a2 += t3.z * Fj[14]; a3 += t3.w * Fj[15];
                float v = (a0 + a1) + (a2 + a3);
                Pp[i][j] = v;
                g_Pp[t][i][j] = v;
            }
            __syncthreads();

            // P3: PHt = Pp * H^T (+ transpose)
            if (tid < 128) {
                const float4* pr = reinterpret_cast<const float4*>(&Pp[r3][0]);
                float4 p0 = pr[0], p1 = pr[1], p2 = pr[2], p3 = pr[3];
                float a0 = 0.f, a1 = 0.f, a2 = 0.f, a3 = 0.f;
                a0 += p0.x * Hc[0];  a1 += p0.y * Hc[1];  a2 += p0.z * Hc[2];  a3 += p0.w * Hc[3];
                a0 += p1.x * Hc[4];  a1 += p1.y * Hc[5];  a2 += p1.z * Hc[6];  a3 += p1.w * Hc[7];
                a0 += p2.x * Hc[8];  a1 += p2.y * Hc[9];  a2 += p2.z * Hc[10]; a3 += p2.w * Hc[11];
                a0 += p3.x * Hc[12]; a1 += p3.y * Hc[13]; a2 += p3.z * Hc[14]; a3 += p3.w * Hc[15];
                float v = (a0 + a1) + (a2 + a3);
                PHt[r3][c3]  = v;
                PHtT[c3][r3] = v;
            }
            __syncthreads();

            // P4: warp 0: S = H*PHt + R, shuffle Gauss-Jordan -> Sinv
            if (tid < 32) {
                float s0 = Rr0, s1 = Rr1, b0 = 0.f, b1 = 0.f;
                #pragma unroll
                for (int q = 0; q < 16; q += 2) {
                    s0 += Hr[q]     * PHtT[lc0][q];
                    b0 += Hr[q + 1] * PHtT[lc0][q + 1];
                    s1 += Hr[q]     * PHtT[lc1][q];
                    b1 += Hr[q + 1] * PHtT[lc1][q + 1];
                }
                s0 += b0; s1 += b1;
                float v0 = (lr == lc0) ? 1.0f : 0.0f;
                float v1 = (lr == lc1) ? 1.0f : 0.0f;

                #pragma unroll
                for (int k = 0; k < 8; ++k) {
                    const int srcrow = (k << 2) + lc0;
                    float rk0 = __shfl_sync(0xffffffffu, s0, srcrow);
                    float rk1 = __shfl_sync(0xffffffffu, s1, srcrow);
                    float rv0 = __shfl_sync(0xffffffffu, v0, srcrow);
                    float rv1 = __shfl_sync(0xffffffffu, v1, srcrow);
                    float sel = (k < 4) ? s0 : s1;
                    float piv = __shfl_sync(0xffffffffu, sel, (k << 2) + (k & 3));
                    float ck  = __shfl_sync(0xffffffffu, sel, (tid & ~3) + (k & 3));
                    float pinv = 1.0f / piv;
                    float n0 = rk0 * pinv, n1 = rk1 * pinv;
                    float m0 = rv0 * pinv, m1 = rv1 * pinv;
                    const bool isk = (lr == k);
                    s0 = isk ? n0 : s0 - ck * n0;
                    s1 = isk ? n1 : s1 - ck * n1;
                    v0 = isk ? m0 : v0 - ck * m0;
                    v1 = isk ? m1 : v1 - ck * m1;
                }
                Sinv[lr][lc0] = v0;
                Sinv[lr][lc1] = v1;
            }
            __syncthreads();

            // P5: K = PHt * Sinv
            if (tid < 128) {
                const float4* pr = reinterpret_cast<const float4*>(&PHt[r3][0]);
                const float4* sr = reinterpret_cast<const float4*>(&Sinv[c3][0]);
                float4 p0 = pr[0], p1 = pr[1];
                float4 q0 = sr[0], q1 = sr[1];
                float a0 = p0.x * q0.x + p0.y * q0.y;
                float a1 = p0.z * q0.z + p0.w * q0.w;
                float a2 = p1.x * q1.x + p1.y * q1.y;
                float a3 = p1.z * q1.z + p1.w * q1.w;
                float v = (a0 + a1) + (a2 + a3);
                Ks[r3][c3] = v;
                g_K[t][r3][c3] = v;
            }
            __threadfence();            // make g_K[t] (and earlier g_Pp) visible
            __syncthreads();
            if (tid == 0) atomicExch(&g_progress, t + 1);   // publish step t

            // P6: P_f = Pp - K * PHt^T
            {
                const float4* kr = reinterpret_cast<const float4*>(&Ks[i][0]);
                const float4* pr = reinterpret_cast<const float4*>(&PHt[j][0]);
                float4 k0 = kr[0], k1 = kr[1];
                float4 p0 = pr[0], p1 = pr[1];
                float a0 = k0.x * p0.x + k0.y * p0.y;
                float a1 = k0.z * p0.z + k0.w * p0.w;
                float a2 = k1.x * p1.x + k1.y * p1.y;
                float a3 = k1.z * p1.z + k1.w * p1.w;
                float v = Pp[i][j] - ((a0 + a1) + (a2 + a3));
                Psh[i][j] = v;
                g_Pf[t][i][j] = v;
            }
            __syncthreads();
        }
        return;
    }

    // ===================== worker CTA =====================
    const int w = blockIdx.x - 1;              // 0..127

    // backward ring + forward uys overlay
    __shared__ __align__(16) unsigned char smem_raw[30720];
    float4 (*uys)[16][3]  = reinterpret_cast<float4(*)[16][3]>(smem_raw + 18432);
    float4 (*gst)[16][5]  = reinterpret_cast<float4(*)[16][5]>(smem_raw);
    float  (*sfst)[320]   = reinterpret_cast<float(*)[320]>(smem_raw + 10240);
    float  (*spst)[320]   = reinterpret_cast<float(*)[320]>(smem_raw + 20480);

    // forward working arrays
    __shared__ float Hs[8][17], Fs[16][17], FsT[16][17], Msh[16][17], Bcs[16][4];
    __shared__ __align__(16) float Ws[16][20];
    __shared__ __align__(16) float Ksm[16][8];
    __shared__ __align__(16) float Vs[16][4];
    // G-phase arrays
    __shared__ float Pf_s[16][16], tmps[16][16];
    __shared__ float aug[16][33];
    __shared__ float colk[16], rowk[32];

    const int warp = tid >> 5;
    const int lane = tid & 31;
    const int sub  = lane >> 4;
    const int li   = lane & 15;
    const int bat  = warp * 2 + sub;           // 0..15
    const int b    = w * 16 + bat;
    const int i = tid >> 4, j = tid & 15;

    {
        float f = ((i == j) ? 1.0f : 0.0f) + DT * A[i * 16 + j];
        Fs[i][j]  = f;
        FsT[j][i] = f;
        if (tid < 128) Hs[tid >> 4][tid & 15] = H[tid];
        if (tid < 64)  Bcs[tid >> 2][tid & 3] = Bc[tid];
    }

    float Frow[16], Bcd[4];
    #pragma unroll
    for (int k = 0; k < 16; ++k) Frow[k] = ((li == k) ? 1.0f : 0.0f) + DT * A[li * 16 + k];
    #pragma unroll
    for (int c = 0; c < 4; ++c) Bcd[c] = DT * Bc[li * 4 + c];

    const float4* __restrict__ cb4 = reinterpret_cast<const float4*>(controls); // batch*128 + t
    const float4* __restrict__ ob4 = reinterpret_cast<const float4*>(obs);      // batch*256 + 2t
    const float4* __restrict__ Gb  = reinterpret_cast<const float4*>(&g_G[0][0][0]);

    auto issue_uy = [&](int t) {
        const int s = t & (ST - 1);
        if (tid < 48) {
            const int bt = tid / 3, slot = tid % 3;
            const int bb = w * 16 + bt;
            const float4* src = (slot == 0) ? (cb4 + bb * 128 + t)
                                            : (ob4 + bb * 256 + 2 * t + (slot - 1));
            cp16(&uys[s][bt][slot], src);
        }
    };

    auto issue_bwd = [&](int r) {
        const int s = r & (ST - 1);
        const int t = 126 - r;
        if (tid < 64) {
            const int row = tid >> 2, slot = tid & 3;
            cp16(&gst[s][row][slot], Gb + t * 64 + row * 4 + slot);
        } else if (tid < 128) {
            const int q = tid - 64, bt = q >> 2, part = q & 3;
            const int bb = w * 16 + bt;
            const float4* src = reinterpret_cast<const float4*>(&g_sf[0][0][0])
                                + ((size_t)t * 2048 + bb) * 4 + part;
            cp16(&sfst[s][bt * 20 + part * 4], src);
        } else if (tid < 192) {
            const int q = tid - 128, bt = q >> 2, part = q & 3;
            const int bb = w * 16 + bt;
            const float4* src = reinterpret_cast<const float4*>(&g_sp[0][0][0])
                                + ((size_t)(t + 1) * 2048 + bb) * 4 + part;
            cp16(&spst[s][bt * 20 + part * 4], src);
        }
    };

    float s = state0[b * 16 + li];
    __syncthreads();

    #pragma unroll
    for (int p = 0; p < ST - 1; ++p) { issue_uy(p); cp_commit(); }

    // ================= forward filter (consumes K_t as produced) =================
    for (int t = 0; t < 128; ++t) {
        if (tid == 0) {
            while (atomicAdd(&g_progress, 0) < t + 1) __nanosleep(40);
            __threadfence();
        }
        __syncthreads();

        // phase A1: Msh = I - K H   (K via L2 to avoid any stale L1)
        {
            float4 ka = __ldcg(reinterpret_cast<const float4*>(&g_K[t][i][0]));
            float4 kb = __ldcg(reinterpret_cast<const float4*>(&g_K[t][i][4]));
            float m = (i == j) ? 1.0f : 0.0f;
            m -= ka.x * Hs[0][j] + ka.y * Hs[1][j] + ka.z * Hs[2][j] + ka.w * Hs[3][j];
            m -= kb.x * Hs[4][j] + kb.y * Hs[5][j] + kb.z * Hs[6][j] + kb.w * Hs[7][j];
            Msh[i][j] = m;
            if (j < 8) Ksm[i][j] = __ldcg(&g_K[t][i][j]);
        }
        __syncthreads();

        // phase A2: Ws = Msh * F, Vs = DT * Msh * Bc
        {
            float a0 = 0.f, a1 = 0.f, a2 = 0.f, a3 = 0.f;
            #pragma unroll
            for (int k = 0; k < 16; k += 4) {
                a0 += Msh[i][k + 0] * FsT[j][k + 0];
                a1 += Msh[i][k + 1] * FsT[j][k + 1];
                a2 += Msh[i][k + 2] * FsT[j][k + 2];
                a3 += Msh[i][k + 3] * FsT[j][k + 3];
            }
            Ws[i][j] = (a0 + a1) + (a2 + a3);
        }
        if (tid < 64) {
            const int i2 = tid >> 2, c2 = tid & 3;
            float v = 0.f;
            #pragma unroll
            for (int k = 0; k < 16; ++k) v += Msh[i2][k] * Bcs[k][c2];
            Vs[i2][c2] = DT * v;
        }
        if (t + ST - 1 < 128) issue_uy(t + ST - 1);   // FIX: guard OOB prefetch
        cp_commit();
        cp_wait<ST - 2>();
        __syncthreads();

        // phase B: per-warp filter step
        const int st = t & (ST - 1);
        const float4* Wr = reinterpret_cast<const float4*>(&Ws[li][0]);
        float4 w0 = Wr[0], w1 = Wr[1], w2 = Wr[2], w3 = Wr[3];
        const float4* Kr = reinterpret_cast<const float4*>(&Ksm[li][0]);
        float4 kk0 = Kr[0], kk1 = Kr[1];
        float4 vv = *reinterpret_cast<const float4*>(&Vs[li][0]);
        float4 uu = uys[st][bat][0], ya = uys[st][bat][1], yc = uys[st][bat][2];

        float sv[16];
        #pragma unroll
        for (int k = 0; k < 16; ++k) sv[k] = __shfl_sync(0xffffffffu, s, k, 16);

        // s_p = F s + DT Bc u
        float p0 = Frow[0]  * sv[0]  + Frow[1]  * sv[1];
        float p1 = Frow[2]  * sv[2]  + Frow[3]  * sv[3];
        float p2 = Frow[4]  * sv[4]  + Frow[5]  * sv[5];
        float p3 = Frow[6]  * sv[6]  + Frow[7]  * sv[7];
        p0 += Frow[8]  * sv[8]  + Frow[9]  * sv[9];
        p1 += Frow[10] * sv[10] + Frow[11] * sv[11];
        p2 += Frow[12] * sv[12] + Frow[13] * sv[13];
        p3 += Frow[14] * sv[14] + Frow[15] * sv[15];
        p0 += Bcd[0] * uu.x + Bcd[1] * uu.y;
        p1 += Bcd[2] * uu.z + Bcd[3] * uu.w;
        const float sp = (p0 + p1) + (p2 + p3);

        // s_new = W s + V u + K y
        float a0 = w0.x * sv[0]  + w0.y * sv[1];
        float a1 = w0.z * sv[2]  + w0.w * sv[3];
        float a2 = w1.x * sv[4]  + w1.y * sv[5];
        float a3 = w1.z * sv[6]  + w1.w * sv[7];
        a0 += w2.x * sv[8]  + w2.y * sv[9];
        a1 += w2.z * sv[10] + w2.w * sv[11];
        a2 += w3.x * sv[12] + w3.y * sv[13];
        a3 += w3.z * sv[14] + w3.w * sv[15];
        a0 += vv.x * uu.x + vv.y * uu.y;
        a1 += vv.z * uu.z + vv.w * uu.w;
        a2 += kk0.x * ya.x + kk0.y * ya.y;
        a3 += kk0.z * ya.z + kk0.w * ya.w;
        a0 += kk1.x * yc.x + kk1.y * yc.y;
        a1 += kk1.z * yc.z + kk1.w * yc.w;
        const float sn = (a0 + a1) + (a2 + a3);

        g_sf[t][b][li] = sn;
        g_sp[t][b][li] = sp;
        s = sn;
    }

    cp_wait<0>();
    __syncthreads();

    float ss = s;   // s_s[127] = s_f[127]
    float* ob = out + (size_t)b * 2048 + li;
    ob[127 * 16] = ss;

    // ================= G_w tile (t = w), k2's proven code =================
    if (w < 127) {
        Pf_s[i][j]     = __ldcg(&g_Pf[w][i][j]);
        aug[i][j]      = __ldcg(&g_Pp[w + 1][i][j]);
        aug[i][16 + j] = (i == j) ? 1.0f : 0.0f;
        __syncthreads();

        #pragma unroll 1
        for (int k = 0; k < 16; ++k) {
            if (tid < 16)                    colk[tid]      = aug[tid][k];
            else if (tid >= 32 && tid < 64)  rowk[tid - 32] = aug[k][tid - 32];
            __syncthreads();
            float piv = 1.0f / colk[k];
            if (i == k) {
                aug[k][j]      = rowk[j]      * piv;
                aug[k][j + 16] = rowk[j + 16] * piv;
            } else {
                float fct = colk[i] * piv;
                aug[i][j]      -= fct * rowk[j];
                aug[i][j + 16] -= fct * rowk[j + 16];
            }
            __syncthreads();
        }

        {
            float a = 0.f;
            #pragma unroll
            for (int k = 0; k < 16; ++k) a += Pf_s[i][k] * Fs[j][k];
            tmps[i][j] = a;
        }
        __syncthreads();
        {
            float g = 0.f;
            #pragma unroll
            for (int k = 0; k < 16; ++k) g += tmps[i][k] * aug[k][16 + j];
            g_G[w][i][j] = g;
        }
    }

    // ================= grid sync over workers =================
    __threadfence();
    __syncthreads();
    if (tid == 0) {
        atomicAdd(&g_done, 1);
        while (atomicAdd(&g_done, 0) < 128) __nanosleep(80);
        __threadfence();
    }
    __syncthreads();

    // ================= backward smoother (R5 proven) =================
    #pragma unroll
    for (int p = 0; p < ST - 1; ++p) { issue_bwd(p); cp_commit(); }

    for (int r = 0; r < 127; ++r) {      // t = 126 - r
        cp_wait<ST - 2>();
        __syncthreads();

        const int st = r & (ST - 1);
        float4 gg0 = gst[st][li][0], gg1 = gst[st][li][1];
        float4 gg2 = gst[st][li][2], gg3 = gst[st][li][3];
        const float sfc = sfst[st][bat * 20 + li];
        const float spc = spst[st][bat * 20 + li];

        if (r + ST - 1 < 127) issue_bwd(r + ST - 1);
        cp_commit();

        const float d = ss - spc;
        float dv[16];
        #pragma unroll
        for (int k = 0; k < 16; ++k) dv[k] = __shfl_sync(0xffffffffu, d, k, 16);

        float a0 = gg0.x * dv[0]  + gg0.y * dv[1];
        float a1 = gg0.z * dv[2]  + gg0.w * dv[3];
        float a2 = gg1.x * dv[4]  + gg1.y * dv[5];
        float a3 = gg1.z * dv[6]  + gg1.w * dv[7];
        a0 += gg2.x * dv[8]  + gg2.y * dv[9];
        a1 += gg2.z * dv[10] + gg2.w * dv[11];
        a2 += gg3.x * dv[12] + gg3.y * dv[13];
        a3 += gg3.z * dv[14] + gg3.w * dv[15];

        ss = sfc + ((a0 + a1) + (a2 + a3));
        ob[(126 - r) * 16] = ss;
    }
}

// =====================================================================
extern "C" void kernel_launch(void* const* d_in, const int* in_sizes, int n_in,
                              void* d_out, int out_size)
{
    const float* state0   = (const float*)d_in[0];
    const float* P0       = (const float*)d_in[1];
    const float* controls = (const float*)d_in[2];
    const float* obs      = (const float*)d_in[3];
    const float* A        = (const float*)d_in[4];
    const float* Bc       = (const float*)d_in[5];
    const float* H        = (const float*)d_in[6];
    const float* Q        = (const float*)d_in[7];
    const float* R        = (const float*)d_in[8];
    float* out = (float*)d_out;

    init_sync<<<1, 1>>>();
    fused_kernel<<<129, 256>>>(state0, controls, obs, A, Bc, H, Q, R, P0, out);
}